// round 15
// baseline (speedup 1.0000x reference)
#include <cuda_runtime.h>
#include <cstdint>

#define ORD   24
#define TLEN  168
#define DD    512
#define SS    336
#define BB    256
#define NTS   21              // n-tiles of 8 t
#define LSTR  172             // smem lane stride in floats (conflict-free LDS.128)
#define NTILE 1024            // tiles = batch x d-quarter
#define GRIDB 592             // 148 SMs x 4 CTAs, one persistent wave

__device__ int g_counter = 0;   // work-steal counter (self-resets per launch)
__device__ int g_done    = 0;

// ---------------------------------------------------------------------------
__device__ __forceinline__ uint32_t to_tf32(float v) {
    uint32_t u;
    asm("cvt.rna.tf32.f32 %0, %1;" : "=r"(u) : "f"(v));
    return u;
}

// m16n8k8 tf32 MMA (sm_80+ base feature; valid on compute_103).
__device__ __forceinline__ void mma8(float& d0, float& d1, float& d2, float& d3,
                                     uint32_t a0, uint32_t a1, uint32_t a2,
                                     uint32_t a3, uint32_t b0, uint32_t b1) {
    asm volatile(
        "mma.sync.aligned.m16n8k8.row.col.f32.tf32.tf32.f32 "
        "{%0,%1,%2,%3}, {%4,%5,%6,%7}, {%8,%9}, {%0,%1,%2,%3};"
        : "+f"(d0), "+f"(d1), "+f"(d2), "+f"(d3)
        : "r"(a0), "r"(a1), "r"(a2), "r"(a3), "r"(b0), "r"(b1));
}

// ---------------------------------------------------------------------------
// Fused persistent kernel (R12 skeleton + fragment-order B tables).
//   Prologue (threads 0..31): thread j runs the exact-fp32 coefficient
//   recurrence for column j (j==24 = bias; j>=25 zeros), writing 3xTF32
//   hi/lo tables DIRECTLY IN FRAGMENT ORDER (validated in R13):
//     lane = (t&7)*4 + (j&3),  p = (j>>3)*2 + ((j>>2)&1)
//     sB[lane*LSTR + (t>>3)*8 + p]
//   so a warp's whole B fragment per n-tile is 2 conflict-free LDS.128
//   per table.
//   Mainloop: tile = (batch, dq); warp w owns d rows [32w,32w+32) x 168 t.
//   A fragments (ctx hi/lo) from global with batched LDGs. 3xTF32 with
//   separate accumulators: D = Ah*Bh + Ah*Bl + Al*Bh.
// ---------------------------------------------------------------------------
__global__ void __launch_bounds__(128, 4)
ar_fused_kernel(const float* __restrict__ x, const float* __restrict__ W,
                const float* __restrict__ bptr, float* __restrict__ out) {
    __shared__ __align__(16) float sBh[32 * LSTR];   // 22.0 KB
    __shared__ __align__(16) float sBl[32 * LSTR];   // 22.0 KB
    __shared__ int s_tile;

    const int tid  = threadIdx.x;
    const int warp = tid >> 5;
    const int lane = tid & 31;
    const int g    = lane >> 2;          // groupID 0..7
    const int tg   = lane & 3;           // thread-in-group 0..3

    // ---- coef prologue (threads 0..31), fragment-order writes ----
    if (tid < 32) {
        const int j  = tid;
        const int pl = (j >> 3) * 2 + ((j >> 2) & 1);
        const int jl = j & 3;

        if (j >= 25) {
            for (int t = 0; t < TLEN; t++) {
                const int of = ((t & 7) * 4 + jl) * LSTR + (t >> 3) * 8 + pl;
                sBh[of] = 0.0f;
                sBl[of] = 0.0f;
            }
        } else {
            float w[ORD];
#pragma unroll
            for (int i = 0; i < ORD; i++) w[i] = W[i];
            const float bias = bptr[0];

            float m[ORD];
#pragma unroll
            for (int i = 0; i < ORD; i++)
                m[i] = (j < ORD && i == j) ? 1.0f : 0.0f;

            for (int t = 0; t < TLEN; t++) {
                float p[24];
#pragma unroll
                for (int i = 0; i < 23; i++) p[i] = w[i] * m[i];
                p[23] = 0.0f;
#pragma unroll
                for (int k = 0; k < 12; k++) p[k] = p[2 * k] + p[2 * k + 1];
#pragma unroll
                for (int k = 0; k < 6; k++)  p[k] = p[2 * k] + p[2 * k + 1];
#pragma unroll
                for (int k = 0; k < 3; k++)  p[k] = p[2 * k] + p[2 * k + 1];
                float y = (p[0] + p[1]) + p[2];
                y = fmaf(w[23], m[23], y);
                if (j == 24) y += bias;

                const float hi = __uint_as_float(to_tf32(y));
                const int of = ((t & 7) * 4 + jl) * LSTR + (t >> 3) * 8 + pl;
                sBh[of] = hi;
                sBl[of] = __uint_as_float(to_tf32(y - hi));

#pragma unroll
                for (int i = 0; i < ORD - 1; i++) m[i] = m[i + 1];
                m[ORD - 1] = y;          // recurrence stays full fp32
            }
        }
    }
    __syncthreads();

    const float4* bh4 = reinterpret_cast<const float4*>(&sBh[lane * LSTR]);
    const float4* bl4 = reinterpret_cast<const float4*>(&sBl[lane * LSTR]);

    int tile = blockIdx.x;               // first tile pre-assigned

    for (;;) {
        const int batch = tile >> 2, dq = tile & 3;
        const float* xb =
            x + ((size_t)batch * SS + (SS - ORD)) * DD + dq * 128 + warp * 32;

        // ---- A fragments: batched raw LDGs, then convert ----
        uint32_t ah[2][4][4], al[2][3][4];
#pragma unroll
        for (int mi = 0; mi < 2; mi++) {
            const int r0 = mi * 16 + g;
            const int r1 = r0 + 8;
            float v[3][4];
#pragma unroll
            for (int kc = 0; kc < 3; kc++) {
                const int ka = kc * 8 + tg, kb = ka + 4;
                v[kc][0] = xb[(size_t)ka * DD + r0];
                v[kc][1] = xb[(size_t)ka * DD + r1];
                v[kc][2] = xb[(size_t)kb * DD + r0];
                v[kc][3] = xb[(size_t)kb * DD + r1];
            }
#pragma unroll
            for (int kc = 0; kc < 3; kc++) {
#pragma unroll
                for (int r = 0; r < 4; r++) {
                    const uint32_t h = to_tf32(v[kc][r]);
                    ah[mi][kc][r] = h;
                    al[mi][kc][r] = to_tf32(v[kc][r] - __uint_as_float(h));
                }
            }
            const uint32_t one = (tg == 0) ? __float_as_uint(1.0f) : 0u;
            ah[mi][3][0] = one;          // bias column at k=24
            ah[mi][3][1] = one;
            ah[mi][3][2] = 0u;
            ah[mi][3][3] = 0u;
        }

        float* ob = out + (size_t)batch * TLEN * DD + dq * 128 + warp * 32;

        // ---- 21 n-tiles of 8 t ----
#pragma unroll 1
        for (int nt = 0; nt < NTS; nt++) {
            const int t0 = nt * 8;

            // B fragment: 4 conflict-free LDS.128
            const float4 h0 = bh4[nt * 2], h1 = bh4[nt * 2 + 1];
            const float4 l0 = bl4[nt * 2], l1 = bl4[nt * 2 + 1];
            const uint32_t bh[4][2] = {
                {__float_as_uint(h0.x), __float_as_uint(h0.y)},
                {__float_as_uint(h0.z), __float_as_uint(h0.w)},
                {__float_as_uint(h1.x), __float_as_uint(h1.y)},
                {__float_as_uint(h1.z), __float_as_uint(h1.w)}};
            const uint32_t bl[4][2] = {
                {__float_as_uint(l0.x), __float_as_uint(l0.y)},
                {__float_as_uint(l0.z), __float_as_uint(l0.w)},
                {__float_as_uint(l1.x), __float_as_uint(l1.y)},
                {__float_as_uint(l1.z), __float_as_uint(l1.w)}};

            // 6 independent accumulator chains (<=4 MMAs deep each)
            float aH0[4] = {0, 0, 0, 0}, aM0[4] = {0, 0, 0, 0},
                  aL0[4] = {0, 0, 0, 0};
            float aH1[4] = {0, 0, 0, 0}, aM1[4] = {0, 0, 0, 0},
                  aL1[4] = {0, 0, 0, 0};
#pragma unroll
            for (int kc = 0; kc < 4; kc++) {
                mma8(aH0[0], aH0[1], aH0[2], aH0[3],
                     ah[0][kc][0], ah[0][kc][1], ah[0][kc][2], ah[0][kc][3],
                     bh[kc][0], bh[kc][1]);
                mma8(aH1[0], aH1[1], aH1[2], aH1[3],
                     ah[1][kc][0], ah[1][kc][1], ah[1][kc][2], ah[1][kc][3],
                     bh[kc][0], bh[kc][1]);
                mma8(aM0[0], aM0[1], aM0[2], aM0[3],
                     ah[0][kc][0], ah[0][kc][1], ah[0][kc][2], ah[0][kc][3],
                     bl[kc][0], bl[kc][1]);
                mma8(aM1[0], aM1[1], aM1[2], aM1[3],
                     ah[1][kc][0], ah[1][kc][1], ah[1][kc][2], ah[1][kc][3],
                     bl[kc][0], bl[kc][1]);
                if (kc < 3) {            // kc=3 has all-zero A-lo
                    mma8(aL0[0], aL0[1], aL0[2], aL0[3],
                         al[0][kc][0], al[0][kc][1], al[0][kc][2],
                         al[0][kc][3], bh[kc][0], bh[kc][1]);
                    mma8(aL1[0], aL1[1], aL1[2], aL1[3],
                         al[1][kc][0], al[1][kc][1], al[1][kc][2],
                         al[1][kc][3], bh[kc][0], bh[kc][1]);
                }
            }

            const size_t tq = (size_t)(t0 + tg * 2) * DD;
            __stcs(ob + tq + g,           (aH0[0] + aM0[0]) + aL0[0]);
            __stcs(ob + tq + DD + g,      (aH0[1] + aM0[1]) + aL0[1]);
            __stcs(ob + tq + g + 8,       (aH0[2] + aM0[2]) + aL0[2]);
            __stcs(ob + tq + DD + g + 8,  (aH0[3] + aM0[3]) + aL0[3]);
            __stcs(ob + tq + g + 16,      (aH1[0] + aM1[0]) + aL1[0]);
            __stcs(ob + tq + DD + g + 16, (aH1[1] + aM1[1]) + aL1[1]);
            __stcs(ob + tq + g + 24,      (aH1[2] + aM1[2]) + aL1[2]);
            __stcs(ob + tq + DD + g + 24, (aH1[3] + aM1[3]) + aL1[3]);
        }

        // ---- steal next tile (CTA-level) ----
        __syncthreads();
        if (tid == 0) s_tile = GRIDB + atomicAdd(&g_counter, 1);
        __syncthreads();
        tile = s_tile;
        if (tile >= NTILE) break;
    }

    // ---- self-reset so each graph replay starts identically ----
    if (tid == 0) {
        const int d = atomicAdd(&g_done, 1);
        if (d == GRIDB - 1) {
            atomicExch(&g_counter, 0);
            atomicExch(&g_done, 0);
        }
    }
}

// ---------------------------------------------------------------------------
extern "C" void kernel_launch(void* const* d_in, const int* in_sizes, int n_in,
                              void* d_out, int out_size) {
    const float* x = (const float*)d_in[0];   // [256, 336, 512] f32
    const float* W = (const float*)d_in[1];   // [24, 1] f32
    const float* b = (const float*)d_in[2];   // [1] f32
    float* out = (float*)d_out;               // [256, 168, 512] f32

    ar_fused_kernel<<<GRIDB, 128>>>(x, W, b, out);
}

// round 16
// speedup vs baseline: 1.0544x; 1.0544x over previous
#include <cuda_runtime.h>
#include <cstdint>

#define ORD   24
#define TLEN  168
#define DD    512
#define SS    336
#define BB    256
#define NTS   21              // n-tiles of 8 t
#define LSTR  172             // B-table lane stride in floats (conflict-free LDS.128)
#define SSTR  36              // staging row stride in floats (conflict-free STS)
#define NTILE 1024            // tiles = batch x d-quarter
#define GRIDB 592             // 148 SMs x 4 CTAs, one persistent wave

__device__ int g_counter = 0;   // work-steal counter (self-resets per launch)
__device__ int g_done    = 0;

// ---------------------------------------------------------------------------
__device__ __forceinline__ uint32_t to_tf32(float v) {
    uint32_t u;
    asm("cvt.rna.tf32.f32 %0, %1;" : "=r"(u) : "f"(v));
    return u;
}

// m16n8k8 tf32 MMA (sm_80+ base feature; valid on compute_103).
__device__ __forceinline__ void mma8(float& d0, float& d1, float& d2, float& d3,
                                     uint32_t a0, uint32_t a1, uint32_t a2,
                                     uint32_t a3, uint32_t b0, uint32_t b1) {
    asm volatile(
        "mma.sync.aligned.m16n8k8.row.col.f32.tf32.tf32.f32 "
        "{%0,%1,%2,%3}, {%4,%5,%6,%7}, {%8,%9}, {%0,%1,%2,%3};"
        : "+f"(d0), "+f"(d1), "+f"(d2), "+f"(d3)
        : "r"(a0), "r"(a1), "r"(a2), "r"(a3), "r"(b0), "r"(b1));
}

// ---------------------------------------------------------------------------
// Fused persistent kernel (R12 skeleton + fragment-order B + COALESCED STORES).
//   Prologue (threads 0..31): thread j runs the exact-fp32 coefficient
//   recurrence for column j (j==24 = bias; j>=25 zeros), writing 3xTF32
//   hi/lo tables in MMA fragment order:
//     lane = (t&7)*4 + (j&3),  p = (j>>3)*2 + ((j>>2)&1)
//     sB[lane*LSTR + (t>>3)*8 + p]
//   Mainloop: tile = (batch, dq); warp w owns d rows [32w,32w+32) x 168 t.
//   3xTF32 with separate accumulators: D = Ah*Bh + Ah*Bl + Al*Bh.
//   Epilogue per n-tile: STS into a per-warp 8x36 staging tile (conflict-
//   free), syncwarp, 2x LDS.128 + 2x coalesced STG.128 (4 full lines each).
//   Global-store wavefronts per n-tile drop 32 -> 8.
// ---------------------------------------------------------------------------
__global__ void __launch_bounds__(128, 4)
ar_fused_kernel(const float* __restrict__ x, const float* __restrict__ W,
                const float* __restrict__ bptr, float* __restrict__ out) {
    __shared__ __align__(16) float sBh[32 * LSTR];     // 22.0 KB
    __shared__ __align__(16) float sBl[32 * LSTR];     // 22.0 KB
    __shared__ __align__(16) float sst[4][8 * SSTR];   // 4.5 KB staging
    __shared__ int s_tile;

    const int tid  = threadIdx.x;
    const int warp = tid >> 5;
    const int lane = tid & 31;
    const int g    = lane >> 2;          // groupID 0..7
    const int tg   = lane & 3;           // thread-in-group 0..3

    // ---- coef prologue (threads 0..31), fragment-order writes ----
    if (tid < 32) {
        const int j  = tid;
        const int pl = (j >> 3) * 2 + ((j >> 2) & 1);
        const int jl = j & 3;

        if (j >= 25) {
            for (int t = 0; t < TLEN; t++) {
                const int of = ((t & 7) * 4 + jl) * LSTR + (t >> 3) * 8 + pl;
                sBh[of] = 0.0f;
                sBl[of] = 0.0f;
            }
        } else {
            float w[ORD];
#pragma unroll
            for (int i = 0; i < ORD; i++) w[i] = W[i];
            const float bias = bptr[0];

            float m[ORD];
#pragma unroll
            for (int i = 0; i < ORD; i++)
                m[i] = (j < ORD && i == j) ? 1.0f : 0.0f;

            for (int t = 0; t < TLEN; t++) {
                float p[24];
#pragma unroll
                for (int i = 0; i < 23; i++) p[i] = w[i] * m[i];
                p[23] = 0.0f;
#pragma unroll
                for (int k = 0; k < 12; k++) p[k] = p[2 * k] + p[2 * k + 1];
#pragma unroll
                for (int k = 0; k < 6; k++)  p[k] = p[2 * k] + p[2 * k + 1];
#pragma unroll
                for (int k = 0; k < 3; k++)  p[k] = p[2 * k] + p[2 * k + 1];
                float y = (p[0] + p[1]) + p[2];
                y = fmaf(w[23], m[23], y);
                if (j == 24) y += bias;

                const float hi = __uint_as_float(to_tf32(y));
                const int of = ((t & 7) * 4 + jl) * LSTR + (t >> 3) * 8 + pl;
                sBh[of] = hi;
                sBl[of] = __uint_as_float(to_tf32(y - hi));

#pragma unroll
                for (int i = 0; i < ORD - 1; i++) m[i] = m[i + 1];
                m[ORD - 1] = y;          // recurrence stays full fp32
            }
        }
    }
    __syncthreads();

    const float4* bh4 = reinterpret_cast<const float4*>(&sBh[lane * LSTR]);
    const float4* bl4 = reinterpret_cast<const float4*>(&sBl[lane * LSTR]);
    float* stg = &sst[warp][0];

    int tile = blockIdx.x;               // first tile pre-assigned

    for (;;) {
        const int batch = tile >> 2, dq = tile & 3;
        const float* xb =
            x + ((size_t)batch * SS + (SS - ORD)) * DD + dq * 128 + warp * 32;

        // ---- A fragments: batched raw LDGs, then convert ----
        uint32_t ah[2][4][4], al[2][3][4];
#pragma unroll
        for (int mi = 0; mi < 2; mi++) {
            const int r0 = mi * 16 + g;
            const int r1 = r0 + 8;
            float v[3][4];
#pragma unroll
            for (int kc = 0; kc < 3; kc++) {
                const int ka = kc * 8 + tg, kb = ka + 4;
                v[kc][0] = xb[(size_t)ka * DD + r0];
                v[kc][1] = xb[(size_t)ka * DD + r1];
                v[kc][2] = xb[(size_t)kb * DD + r0];
                v[kc][3] = xb[(size_t)kb * DD + r1];
            }
#pragma unroll
            for (int kc = 0; kc < 3; kc++) {
#pragma unroll
                for (int r = 0; r < 4; r++) {
                    const uint32_t h = to_tf32(v[kc][r]);
                    ah[mi][kc][r] = h;
                    al[mi][kc][r] = to_tf32(v[kc][r] - __uint_as_float(h));
                }
            }
            const uint32_t one = (tg == 0) ? __float_as_uint(1.0f) : 0u;
            ah[mi][3][0] = one;          // bias column at k=24
            ah[mi][3][1] = one;
            ah[mi][3][2] = 0u;
            ah[mi][3][3] = 0u;
        }

        float* ob = out + (size_t)batch * TLEN * DD + dq * 128 + warp * 32;

        // ---- 21 n-tiles of 8 t ----
#pragma unroll 1
        for (int nt = 0; nt < NTS; nt++) {
            const int t0 = nt * 8;

            // B fragment: 4 conflict-free LDS.128
            const float4 h0 = bh4[nt * 2], h1 = bh4[nt * 2 + 1];
            const float4 l0 = bl4[nt * 2], l1 = bl4[nt * 2 + 1];
            const uint32_t bh[4][2] = {
                {__float_as_uint(h0.x), __float_as_uint(h0.y)},
                {__float_as_uint(h0.z), __float_as_uint(h0.w)},
                {__float_as_uint(h1.x), __float_as_uint(h1.y)},
                {__float_as_uint(h1.z), __float_as_uint(h1.w)}};
            const uint32_t bl[4][2] = {
                {__float_as_uint(l0.x), __float_as_uint(l0.y)},
                {__float_as_uint(l0.z), __float_as_uint(l0.w)},
                {__float_as_uint(l1.x), __float_as_uint(l1.y)},
                {__float_as_uint(l1.z), __float_as_uint(l1.w)}};

            // 6 independent accumulator chains (<=4 MMAs deep each)
            float aH0[4] = {0, 0, 0, 0}, aM0[4] = {0, 0, 0, 0},
                  aL0[4] = {0, 0, 0, 0};
            float aH1[4] = {0, 0, 0, 0}, aM1[4] = {0, 0, 0, 0},
                  aL1[4] = {0, 0, 0, 0};
#pragma unroll
            for (int kc = 0; kc < 4; kc++) {
                mma8(aH0[0], aH0[1], aH0[2], aH0[3],
                     ah[0][kc][0], ah[0][kc][1], ah[0][kc][2], ah[0][kc][3],
                     bh[kc][0], bh[kc][1]);
                mma8(aH1[0], aH1[1], aH1[2], aH1[3],
                     ah[1][kc][0], ah[1][kc][1], ah[1][kc][2], ah[1][kc][3],
                     bh[kc][0], bh[kc][1]);
                mma8(aM0[0], aM0[1], aM0[2], aM0[3],
                     ah[0][kc][0], ah[0][kc][1], ah[0][kc][2], ah[0][kc][3],
                     bl[kc][0], bl[kc][1]);
                mma8(aM1[0], aM1[1], aM1[2], aM1[3],
                     ah[1][kc][0], ah[1][kc][1], ah[1][kc][2], ah[1][kc][3],
                     bl[kc][0], bl[kc][1]);
                if (kc < 3) {            // kc=3 has all-zero A-lo
                    mma8(aL0[0], aL0[1], aL0[2], aL0[3],
                         al[0][kc][0], al[0][kc][1], al[0][kc][2],
                         al[0][kc][3], bh[kc][0], bh[kc][1]);
                    mma8(aL1[0], aL1[1], aL1[2], aL1[3],
                         al[1][kc][0], al[1][kc][1], al[1][kc][2],
                         al[1][kc][3], bh[kc][0], bh[kc][1]);
                }
            }

            // ---- epilogue: STS repack -> coalesced STG.128 ----
            __syncwarp();   // prior n-tile's staging LDS fully drained
            {
                const int rA = (2 * tg + 0) * SSTR + g;   // t row 2tg
                const int rB = (2 * tg + 1) * SSTR + g;   // t row 2tg+1
                stg[rA]      = (aH0[0] + aM0[0]) + aL0[0];
                stg[rB]      = (aH0[1] + aM0[1]) + aL0[1];
                stg[rA + 8]  = (aH0[2] + aM0[2]) + aL0[2];
                stg[rB + 8]  = (aH0[3] + aM0[3]) + aL0[3];
                stg[rA + 16] = (aH1[0] + aM1[0]) + aL1[0];
                stg[rB + 16] = (aH1[1] + aM1[1]) + aL1[1];
                stg[rA + 24] = (aH1[2] + aM1[2]) + aL1[2];
                stg[rB + 24] = (aH1[3] + aM1[3]) + aL1[3];
            }
            __syncwarp();   // staging visible to all lanes
#pragma unroll
            for (int s = 0; s < 2; s++) {
                const int r = s * 4 + (lane >> 3);        // t row 0..7
                const int c = (lane & 7) * 4;             // d offset 0..28
                const float4 v =
                    *reinterpret_cast<const float4*>(&stg[r * SSTR + c]);
                __stcs(reinterpret_cast<float4*>(
                           ob + (size_t)(t0 + r) * DD + c), v);
            }
        }

        // ---- steal next tile (CTA-level) ----
        __syncthreads();
        if (tid == 0) s_tile = GRIDB + atomicAdd(&g_counter, 1);
        __syncthreads();
        tile = s_tile;
        if (tile >= NTILE) break;
    }

    // ---- self-reset so each graph replay starts identically ----
    if (tid == 0) {
        const int d = atomicAdd(&g_done, 1);
        if (d == GRIDB - 1) {
            atomicExch(&g_counter, 0);
            atomicExch(&g_done, 0);
        }
    }
}

// ---------------------------------------------------------------------------
extern "C" void kernel_launch(void* const* d_in, const int* in_sizes, int n_in,
                              void* d_out, int out_size) {
    const float* x = (const float*)d_in[0];   // [256, 336, 512] f32
    const float* W = (const float*)d_in[1];   // [24, 1] f32
    const float* b = (const float*)d_in[2];   // [1] f32
    float* out = (float*)d_out;               // [256, 168, 512] f32

    ar_fused_kernel<<<GRIDB, 128>>>(x, W, b, out);
}